// round 13
// baseline (speedup 1.0000x reference)
#include <cuda_runtime.h>
#include <cuda_bf16.h>
#include <math.h>
#include <stdint.h>

#define NTOK 4096
#define NB   128
#define NTILES 1024

// ---------------------------------------------------------------------------
// Scratch (__device__ globals; no allocation allowed)
// ---------------------------------------------------------------------------
__device__ float g_Aq[NTOK], g_Pq[NTOK], g_At[NTOK], g_Pt[NTOK], g_tw[NTOK];
__device__ unsigned int g_done;
__device__ __align__(16) __nv_bfloat16 g_qhi[NTOK * 256];
__device__ __align__(16) __nv_bfloat16 g_qlo[NTOK * 256];
__device__ __align__(16) __nv_bfloat16 g_thi[NTOK * 256];
__device__ __align__(16) __nv_bfloat16 g_tlo[NTOK * 256];

__device__ __forceinline__ uint32_t smem_u32(const void* p) {
    uint32_t a;
    asm("{ .reg .u64 t; cvta.to.shared.u64 t, %1; cvt.u32.u64 %0, t; }" : "=r"(a) : "l"(p));
    return a;
}

// ---------------------------------------------------------------------------
// Kernel A (prep), 1024 threads/block, 512 blocks:
//   blocks [0,256):   fp32->bf16 hi/lo split (2 float4 per thread)
//   blocks [256,384): q-token Bessel stats (one token per warp) + token weights
//   blocks [384,512): t-token Bessel stats
// Also zeroes the GEMM finish counter.
// ---------------------------------------------------------------------------
__global__ __launch_bounds__(1024)
void prep_kernel(const float* __restrict__ q, const float* __restrict__ t,
                 const float* __restrict__ kq, const float* __restrict__ kt,
                 float* __restrict__ entropy_out) {
    const int blk = blockIdx.x, tid = threadIdx.x;
    if (blk == 0 && tid == 0) g_done = 0u;

    if (blk < 256) {
        #pragma unroll
        for (int it = 0; it < 2; it++) {
            int i = blk * 1024 + tid + it * 262144;   // float4 index 0..524287
            bool is_q = i < 262144;
            int j = is_q ? i : i - 262144;
            float4 v = ((const float4*)(is_q ? q : t))[j];
            float x[4] = {v.x, v.y, v.z, v.w};
            uint32_t hi2[2], lo2[2];
            #pragma unroll
            for (int p = 0; p < 2; p++) {
                __nv_bfloat16 h0 = __float2bfloat16(x[p * 2]);
                __nv_bfloat16 h1 = __float2bfloat16(x[p * 2 + 1]);
                __nv_bfloat16 l0 = __float2bfloat16(x[p * 2] - __bfloat162float(h0));
                __nv_bfloat16 l1 = __float2bfloat16(x[p * 2 + 1] - __bfloat162float(h1));
                hi2[p] = (uint32_t)__bfloat16_as_ushort(h0) | ((uint32_t)__bfloat16_as_ushort(h1) << 16);
                lo2[p] = (uint32_t)__bfloat16_as_ushort(l0) | ((uint32_t)__bfloat16_as_ushort(l1) << 16);
            }
            ((uint2*)(is_q ? g_qhi : g_thi))[j] = make_uint2(hi2[0], hi2[1]);
            ((uint2*)(is_q ? g_qlo : g_tlo))[j] = make_uint2(lo2[0], lo2[1]);
        }
        return;
    }

    __shared__ float s_csum[50];
    __shared__ float s_lk[50];
    __shared__ float s_ent[32];

    if (tid < 50) {
        s_csum[tid] = lgammaf((float)(tid + 1)) + lgammaf((float)(tid + 128));
        s_lk[tid]   = logf((float)(tid + 128));
    }
    __syncthreads();

    const int warp = tid >> 5, lane = tid & 31;
    const bool isq = blk < 384;
    const int j = isq ? (blk - 256) * 32 + warp : (blk - 384) * 32 + warp;

    float x = fmaxf((isq ? kq : kt)[j], 1e-6f);
    float L = logf(0.5f * x);

    float t1a = fmaf(2.0f * lane + 127.0f, L, -s_csum[lane]);
    float t2a = t1a + L - s_lk[lane];
    float t1b = -1e30f, t2b = -1e30f;
    if (lane < 18) {
        int k2 = lane + 32;
        t1b = fmaf(2.0f * k2 + 127.0f, L, -s_csum[k2]);
        t2b = t1b + L - s_lk[k2];
    }
    float m1 = fmaxf(t1a, t1b), m2 = fmaxf(t2a, t2b);
    #pragma unroll
    for (int o = 16; o; o >>= 1) {
        m1 = fmaxf(m1, __shfl_xor_sync(0xffffffffu, m1, o));
        m2 = fmaxf(m2, __shfl_xor_sync(0xffffffffu, m2, o));
    }
    float s1 = __expf(t1a - m1) + (lane < 18 ? __expf(t1b - m1) : 0.0f);
    float s2 = __expf(t2a - m2) + (lane < 18 ? __expf(t2b - m2) : 0.0f);
    #pragma unroll
    for (int o = 16; o; o >>= 1) {
        s1 += __shfl_xor_sync(0xffffffffu, s1, o);
        s2 += __shfl_xor_sync(0xffffffffu, s2, o);
    }
    float lb127 = m1 + logf(s1);
    float lb128 = m2 + logf(s2);
    float diff = fminf(fmaxf(lb128 - lb127, -60.0f), 0.0f);
    float A = fminf(fmaxf(expf(diff), 1e-8f), 1.0f - 1e-6f);

    if (isq) {
        if (lane == 0) {
            g_Aq[j] = A;
            g_Pq[j] = A * x;
            float logC = 127.0f * logf(x) - (128.0f * 1.8378770664093454f) - lb127;
            float ent = -logC - x * A;
            entropy_out[j] = ent;
            s_ent[warp] = ent;
        }
        __syncthreads();
        if (tid < 32) {
            float xe = -2.0f * s_ent[tid];
            float m = xe;
            #pragma unroll
            for (int o = 16; o; o >>= 1) m = fmaxf(m, __shfl_xor_sync(0xffffffffu, m, o));
            float e = expf(xe - m);
            float s = e;
            #pragma unroll
            for (int o = 16; o; o >>= 1) s += __shfl_xor_sync(0xffffffffu, s, o);
            g_tw[(blk - 256) * 32 + tid] = e / s;
        }
    } else if (lane == 0) {
        g_At[j] = A;
        g_Pt[j] = A * x;
    }
}

// ---------------------------------------------------------------------------
// Kernel B: split-bf16 mma.sync GEMM (R8-proven: 3-stage cp.async, BK=32,
// one sync per chunk, +2 lookahead), CTA tile 128x128, 8 warps (2x4),
// warp tile 64x32, 2 CTA/SM, fused score epilogue, and a fused FINAL TAIL:
// the last CTA to finish computes logits + log-softmax + loss.
// NOTE: d_out-derived pointers are only 4B-aligned -> tail uses SCALAR ld/st.
// ---------------------------------------------------------------------------
#define STG   32768
#define A_HI  0
#define A_LO  8192
#define B_HI  16384
#define B_LO  24576
#define GEMM_SMEM (3 * STG)

__device__ __forceinline__ uint32_t swz(int r, int c) {
    return (uint32_t)(((r >> 1) * 128) + (((((r & 1) << 2) | c) ^ ((r >> 1) & 7)) << 4));
}
__device__ __forceinline__ void ldmatrix_x4(uint32_t* r, uint32_t addr) {
    asm volatile("ldmatrix.sync.aligned.m8n8.x4.shared.b16 {%0,%1,%2,%3}, [%4];"
                 : "=r"(r[0]), "=r"(r[1]), "=r"(r[2]), "=r"(r[3]) : "r"(addr));
}
__device__ __forceinline__ void mma_16816(float* d, const uint32_t* a, const uint32_t* b) {
    asm volatile(
        "mma.sync.aligned.m16n8k16.row.col.f32.bf16.bf16.f32 "
        "{%0,%1,%2,%3}, {%4,%5,%6,%7}, {%8,%9}, {%0,%1,%2,%3};"
        : "+f"(d[0]), "+f"(d[1]), "+f"(d[2]), "+f"(d[3])
        : "r"(a[0]), "r"(a[1]), "r"(a[2]), "r"(a[3]), "r"(b[0]), "r"(b[1]));
}
#define CP_ASYNC16(dst, src) \
    asm volatile("cp.async.cg.shared.global [%0], [%1], 16;" :: "r"(dst), "l"(src))
#define CP_COMMIT() asm volatile("cp.async.commit_group;" ::: "memory")
#define CP_WAIT1()  asm volatile("cp.async.wait_group 1;" ::: "memory")
#define CP_WAIT0()  asm volatile("cp.async.wait_group 0;" ::: "memory")

__global__ __launch_bounds__(256, 2)
void score_gemm_mma(const float* __restrict__ Kq, const float* __restrict__ Kt,
                    const float* __restrict__ temp,
                    float* __restrict__ score_global,
                    float* __restrict__ logits,
                    float* __restrict__ out_loss) {
    extern __shared__ char smem[];
    const uint32_t sbase = smem_u32(smem);

    const int tid  = threadIdx.x;
    const int wid  = tid >> 5, lane = tid & 31;
    const int wm   = wid >> 2;          // 0..1 (64 rows)
    const int wn   = wid & 3;           // 0..3 (32 cols)
    const int m0   = blockIdx.y * 128, n0 = blockIdx.x * 128;

    const int lg   = lane >> 3;
    const int lrow = (lane & 7) + (lg & 1) * 8;
    const int lkc  = lg >> 1;

    uint32_t aoff[4][2], boff[2][2];
    #pragma unroll
    for (int mf = 0; mf < 4; mf++)
        #pragma unroll
        for (int s = 0; s < 2; s++)
            aoff[mf][s] = swz(wm * 64 + mf * 16 + lrow, s * 2 + lkc);
    #pragma unroll
    for (int pr = 0; pr < 2; pr++)
        #pragma unroll
        for (int s = 0; s < 2; s++)
            boff[pr][s] = swz(wn * 32 + pr * 16 + lrow, s * 2 + lkc);

    float acc[4][4][4];
    #pragma unroll
    for (int i = 0; i < 4; i++)
        #pragma unroll
        for (int j = 0; j < 4; j++)
            #pragma unroll
            for (int r = 0; r < 4; r++) acc[i][j][r] = 0.0f;

    const int srow = tid >> 1;
    const int ch0  = (tid & 1) * 2;
    uint32_t stoff[2];
    stoff[0] = swz(srow, ch0);
    stoff[1] = swz(srow, ch0 + 1);
    const size_t gaRow = (size_t)(m0 + srow) * 256 + ch0 * 8;
    const size_t gbRow = (size_t)(n0 + srow) * 256 + ch0 * 8;

    #define PREFETCH(kc, st) do {                                              \
        const uint32_t sb = sbase + (uint32_t)((st) * STG);                    \
        const size_t gk = (size_t)(kc) * 32;                                   \
        _Pragma("unroll")                                                      \
        for (int c = 0; c < 2; c++) {                                          \
            CP_ASYNC16(sb + A_HI + stoff[c], g_qhi + gaRow + gk + c * 8);      \
            CP_ASYNC16(sb + A_LO + stoff[c], g_qlo + gaRow + gk + c * 8);      \
            CP_ASYNC16(sb + B_HI + stoff[c], g_thi + gbRow + gk + c * 8);      \
            CP_ASYNC16(sb + B_LO + stoff[c], g_tlo + gbRow + gk + c * 8);      \
        }                                                                      \
        CP_COMMIT();                                                           \
    } while (0)

    PREFETCH(0, 0);
    PREFETCH(1, 1);

    #pragma unroll
    for (int kc = 0; kc < 8; kc++) {
        const int cur = kc % 3;
        if (kc < 7) CP_WAIT1(); else CP_WAIT0();
        __syncthreads();
        if (kc < 6) PREFETCH(kc + 2, (kc + 2) % 3);

        const uint32_t so = sbase + (uint32_t)(cur * STG);
        #pragma unroll
        for (int s = 0; s < 2; s++) {
            uint32_t ah[4][4];
            #pragma unroll
            for (int mf = 0; mf < 4; mf++)
                ldmatrix_x4(ah[mf], so + A_HI + aoff[mf][s]);
            uint32_t bh01[4], bh23[4];
            ldmatrix_x4(bh01, so + B_HI + boff[0][s]);
            ldmatrix_x4(bh23, so + B_HI + boff[1][s]);
            uint32_t bh[4][2] = {{bh01[0], bh01[2]}, {bh01[1], bh01[3]},
                                 {bh23[0], bh23[2]}, {bh23[1], bh23[3]}};
            #pragma unroll
            for (int mf = 0; mf < 4; mf++)
                #pragma unroll
                for (int nf = 0; nf < 4; nf++)
                    mma_16816(acc[mf][nf], ah[mf], bh[nf]);
            {
                uint32_t bl01[4], bl23[4];
                ldmatrix_x4(bl01, so + B_LO + boff[0][s]);
                ldmatrix_x4(bl23, so + B_LO + boff[1][s]);
                uint32_t bl[4][2] = {{bl01[0], bl01[2]}, {bl01[1], bl01[3]},
                                     {bl23[0], bl23[2]}, {bl23[1], bl23[3]}};
                #pragma unroll
                for (int mf = 0; mf < 4; mf++)
                    #pragma unroll
                    for (int nf = 0; nf < 4; nf++)
                        mma_16816(acc[mf][nf], ah[mf], bl[nf]);
            }
            {
                uint32_t al[4][4];
                #pragma unroll
                for (int mf = 0; mf < 4; mf++)
                    ldmatrix_x4(al[mf], so + A_LO + aoff[mf][s]);
                #pragma unroll
                for (int mf = 0; mf < 4; mf++)
                    #pragma unroll
                    for (int nf = 0; nf < 4; nf++)
                        mma_16816(acc[mf][nf], al[mf], bh[nf]);
            }
        }
    }

    // ---------------- epilogue ----------------
    {
        float at[8], ktv[8], pt[8];
        #pragma unroll
        for (int nf = 0; nf < 4; nf++)
            #pragma unroll
            for (int rb = 0; rb < 2; rb++) {
                int col = n0 + wn * 32 + nf * 8 + (lane & 3) * 2 + rb;
                at[nf * 2 + rb]  = g_At[col];
                ktv[nf * 2 + rb] = fmaxf(Kt[col], 1e-6f);
                pt[nf * 2 + rb]  = g_Pt[col];
            }

        float part[2] = {0.0f, 0.0f};
        #pragma unroll
        for (int mf = 0; mf < 4; mf++) {
            #pragma unroll
            for (int rh = 0; rh < 2; rh++) {
                int row = m0 + wm * 64 + mf * 16 + (lane >> 2) + rh * 8;
                float aq = g_Aq[row];
                float kq = fmaxf(Kq[row], 1e-6f);
                float pq = g_Pq[row];
                float tw = g_tw[row];
                float mx = -1e30f;
                #pragma unroll
                for (int nf = 0; nf < 4; nf++)
                    #pragma unroll
                    for (int rb = 0; rb < 2; rb++) {
                        int cj = nf * 2 + rb;
                        float beta = 0.5f * (aq * ktv[cj] + at[cj] * kq);
                        float s = fmaf(beta, acc[mf][nf][rh * 2 + rb], -0.5f * (pq + pt[cj]));
                        mx = fmaxf(mx, s);
                    }
                mx = fmaxf(mx, __shfl_xor_sync(0xffffffffu, mx, 1));
                mx = fmaxf(mx, __shfl_xor_sync(0xffffffffu, mx, 2));
                part[mf >> 1] += tw * mx;
            }
        }
        #pragma unroll
        for (int g = 0; g < 2; g++) {
            float v = part[g];
            v += __shfl_xor_sync(0xffffffffu, v, 4);
            v += __shfl_xor_sync(0xffffffffu, v, 8);
            v += __shfl_xor_sync(0xffffffffu, v, 16);
            if (lane == 0)
                score_global[(m0 / 32 + wm * 2 + g) * 128 + n0 / 32 + wn] = v;
        }
    }

    // ---------------- fused tail: last CTA does softmax + loss -------------
    __shared__ unsigned s_last;
    __shared__ float s_red[8];
    __threadfence();                     // publish score_global writes
    __syncthreads();                     // all warps' stores issued
    if (tid == 0) s_last = (atomicAdd(&g_done, 1u) == NTILES - 1u) ? 1u : 0u;
    __syncthreads();
    if (s_last == 0u) return;

    __threadfence();                     // acquire other CTAs' scores
    const float tv = fmaxf(temp[0], 1e-6f);
    const float inv_tv = 1.0f / tv;
    float partial = 0.0f;
    for (int row = wid; row < NB; row += 8) {
        // scalar accesses: score_global/logits are only 4B-aligned (d_out+1+k)
        const float* srow_p = score_global + row * NB + lane * 4;
        float* lrow_p = logits + row * NB + lane * 4;
        float v0 = srow_p[0] * inv_tv, v1 = srow_p[1] * inv_tv;
        float v2 = srow_p[2] * inv_tv, v3 = srow_p[3] * inv_tv;
        lrow_p[0] = v0; lrow_p[1] = v1; lrow_p[2] = v2; lrow_p[3] = v3;
        float m = fmaxf(fmaxf(v0, v1), fmaxf(v2, v3));
        #pragma unroll
        for (int o = 16; o; o >>= 1) m = fmaxf(m, __shfl_xor_sync(0xffffffffu, m, o));
        float e = __expf(v0 - m) + __expf(v1 - m) + __expf(v2 - m) + __expf(v3 - m);
        #pragma unroll
        for (int o = 16; o; o >>= 1) e += __shfl_xor_sync(0xffffffffu, e, o);
        float lse = m + logf(e);
        // diagonal element: col == row -> lane row>>2, slot row&3
        float dloc = (lane == (row >> 2)) ? ((row & 3) == 0 ? v0 : (row & 3) == 1 ? v1
                                           : (row & 3) == 2 ? v2 : v3) : 0.0f;
        float diag = __shfl_sync(0xffffffffu, dloc, row >> 2);
        partial += lse - diag;
    }
    if (lane == 0) s_red[wid] = partial;
    __syncthreads();
    if (tid == 0) {
        float s = 0.0f;
        #pragma unroll
        for (int w = 0; w < 8; w++) s += s_red[w];
        out_loss[0] = s * (1.0f / 128.0f);
    }
}

// ---------------------------------------------------------------------------
// Outputs: [0] loss, [1..16385) logits(128x128), then score(128x128), entropy(128x32)
// ---------------------------------------------------------------------------
extern "C" void kernel_launch(void* const* d_in, const int* in_sizes, int n_in,
                              void* d_out, int out_size) {
    const float* q    = (const float*)d_in[0];
    const float* kq   = (const float*)d_in[1];
    const float* t    = (const float*)d_in[2];
    const float* kt   = (const float*)d_in[3];
    const float* temp = (const float*)d_in[4];

    float* out         = (float*)d_out;
    float* out_loss    = out;
    float* out_logits  = out + 1;
    float* out_score   = out + 1 + 128 * 128;
    float* out_entropy = out + 1 + 2 * 128 * 128;

    static int smem_set = 0;
    if (!smem_set) {
        cudaFuncSetAttribute(score_gemm_mma, cudaFuncAttributeMaxDynamicSharedMemorySize, GEMM_SMEM);
        smem_set = 1;
    }

    prep_kernel<<<512, 1024>>>(q, t, kq, kt, out_entropy);

    dim3 grid(32, 32);
    score_gemm_mma<<<grid, 256, GEMM_SMEM>>>(kq, kt, temp, out_score, out_logits, out_loss);
}

// round 14
// speedup vs baseline: 1.1512x; 1.1512x over previous
#include <cuda_runtime.h>
#include <cuda_bf16.h>
#include <math.h>
#include <stdint.h>

#define NTOK 4096
#define NB   128

// ---------------------------------------------------------------------------
// Scratch (__device__ globals; no allocation allowed)
// ---------------------------------------------------------------------------
__device__ float g_Aq[NTOK], g_Pq[NTOK], g_At[NTOK], g_Pt[NTOK], g_tw[NTOK];
__device__ __align__(16) __nv_bfloat16 g_qhi[NTOK * 256];
__device__ __align__(16) __nv_bfloat16 g_qlo[NTOK * 256];
__device__ __align__(16) __nv_bfloat16 g_thi[NTOK * 256];
__device__ __align__(16) __nv_bfloat16 g_tlo[NTOK * 256];

__device__ __forceinline__ uint32_t smem_u32(const void* p) {
    uint32_t a;
    asm("{ .reg .u64 t; cvta.to.shared.u64 t, %1; cvt.u32.u64 %0, t; }" : "=r"(a) : "l"(p));
    return a;
}

// ---------------------------------------------------------------------------
// Kernel A (prep), 1024 threads/block, 512 blocks:
//   blocks [0,256):   fp32->bf16 hi/lo split (2 float4 per thread)
//   blocks [256,384): q-token Bessel stats (one token per warp) + token weights
//   blocks [384,512): t-token Bessel stats
// Also zeroes the loss accumulator.
// ---------------------------------------------------------------------------
__global__ __launch_bounds__(1024)
void prep_kernel(const float* __restrict__ q, const float* __restrict__ t,
                 const float* __restrict__ kq, const float* __restrict__ kt,
                 float* __restrict__ entropy_out, float* __restrict__ out_loss) {
    const int blk = blockIdx.x, tid = threadIdx.x;
    if (blk == 0 && tid == 0) out_loss[0] = 0.0f;

    if (blk < 256) {
        #pragma unroll
        for (int it = 0; it < 2; it++) {
            int i = blk * 1024 + tid + it * 262144;   // float4 index 0..524287
            bool is_q = i < 262144;
            int j = is_q ? i : i - 262144;
            float4 v = ((const float4*)(is_q ? q : t))[j];
            float x[4] = {v.x, v.y, v.z, v.w};
            uint32_t hi2[2], lo2[2];
            #pragma unroll
            for (int p = 0; p < 2; p++) {
                __nv_bfloat16 h0 = __float2bfloat16(x[p * 2]);
                __nv_bfloat16 h1 = __float2bfloat16(x[p * 2 + 1]);
                __nv_bfloat16 l0 = __float2bfloat16(x[p * 2] - __bfloat162float(h0));
                __nv_bfloat16 l1 = __float2bfloat16(x[p * 2 + 1] - __bfloat162float(h1));
                hi2[p] = (uint32_t)__bfloat16_as_ushort(h0) | ((uint32_t)__bfloat16_as_ushort(h1) << 16);
                lo2[p] = (uint32_t)__bfloat16_as_ushort(l0) | ((uint32_t)__bfloat16_as_ushort(l1) << 16);
            }
            ((uint2*)(is_q ? g_qhi : g_thi))[j] = make_uint2(hi2[0], hi2[1]);
            ((uint2*)(is_q ? g_qlo : g_tlo))[j] = make_uint2(lo2[0], lo2[1]);
        }
        return;
    }

    __shared__ float s_csum[50];
    __shared__ float s_lk[50];
    __shared__ float s_ent[32];

    if (tid < 50) {
        s_csum[tid] = lgammaf((float)(tid + 1)) + lgammaf((float)(tid + 128));
        s_lk[tid]   = logf((float)(tid + 128));
    }
    __syncthreads();

    const int warp = tid >> 5, lane = tid & 31;
    const bool isq = blk < 384;
    const int j = isq ? (blk - 256) * 32 + warp : (blk - 384) * 32 + warp;

    float x = fmaxf((isq ? kq : kt)[j], 1e-6f);
    float L = logf(0.5f * x);

    float t1a = fmaf(2.0f * lane + 127.0f, L, -s_csum[lane]);
    float t2a = t1a + L - s_lk[lane];
    float t1b = -1e30f, t2b = -1e30f;
    if (lane < 18) {
        int k2 = lane + 32;
        t1b = fmaf(2.0f * k2 + 127.0f, L, -s_csum[k2]);
        t2b = t1b + L - s_lk[k2];
    }
    float m1 = fmaxf(t1a, t1b), m2 = fmaxf(t2a, t2b);
    #pragma unroll
    for (int o = 16; o; o >>= 1) {
        m1 = fmaxf(m1, __shfl_xor_sync(0xffffffffu, m1, o));
        m2 = fmaxf(m2, __shfl_xor_sync(0xffffffffu, m2, o));
    }
    float s1 = __expf(t1a - m1) + (lane < 18 ? __expf(t1b - m1) : 0.0f);
    float s2 = __expf(t2a - m2) + (lane < 18 ? __expf(t2b - m2) : 0.0f);
    #pragma unroll
    for (int o = 16; o; o >>= 1) {
        s1 += __shfl_xor_sync(0xffffffffu, s1, o);
        s2 += __shfl_xor_sync(0xffffffffu, s2, o);
    }
    float lb127 = m1 + logf(s1);
    float lb128 = m2 + logf(s2);
    float diff = fminf(fmaxf(lb128 - lb127, -60.0f), 0.0f);
    float A = fminf(fmaxf(expf(diff), 1e-8f), 1.0f - 1e-6f);

    if (isq) {
        if (lane == 0) {
            g_Aq[j] = A;
            g_Pq[j] = A * x;
            float logC = 127.0f * logf(x) - (128.0f * 1.8378770664093454f) - lb127;
            float ent = -logC - x * A;
            entropy_out[j] = ent;
            s_ent[warp] = ent;
        }
        __syncthreads();
        if (tid < 32) {
            float xe = -2.0f * s_ent[tid];
            float m = xe;
            #pragma unroll
            for (int o = 16; o; o >>= 1) m = fmaxf(m, __shfl_xor_sync(0xffffffffu, m, o));
            float e = expf(xe - m);
            float s = e;
            #pragma unroll
            for (int o = 16; o; o >>= 1) s += __shfl_xor_sync(0xffffffffu, s, o);
            g_tw[(blk - 256) * 32 + tid] = e / s;
        }
    } else if (lane == 0) {
        g_At[j] = A;
        g_Pt[j] = A * x;
    }
}

// ---------------------------------------------------------------------------
// Kernel B: split-bf16 mma.sync GEMM (R8 structure: 3-stage cp.async, BK=32,
// one sync per chunk, +2 lookahead). CTA tile 128x128, 8 warps (2x4),
// warp tile 64x32, 2 CTA/SM, fused score epilogue.
// Scheduling changes vs R8:
//  - mma asm is NON-volatile (pure reg ops) so ptxas may interleave MMAs
//    with later ldmatrix, hiding LDSM latency.
//  - B_LO fragments loaded BEFORE the hi*hi MMA block (latency hidden under
//    16 MMAs). Peak live fragments unchanged (32 regs).
// ---------------------------------------------------------------------------
#define STG   32768
#define A_HI  0
#define A_LO  8192
#define B_HI  16384
#define B_LO  24576
#define GEMM_SMEM (3 * STG)

__device__ __forceinline__ uint32_t swz(int r, int c) {
    return (uint32_t)(((r >> 1) * 128) + (((((r & 1) << 2) | c) ^ ((r >> 1) & 7)) << 4));
}
__device__ __forceinline__ void ldmatrix_x4(uint32_t* r, uint32_t addr) {
    asm volatile("ldmatrix.sync.aligned.m8n8.x4.shared.b16 {%0,%1,%2,%3}, [%4];"
                 : "=r"(r[0]), "=r"(r[1]), "=r"(r[2]), "=r"(r[3]) : "r"(addr));
}
// NON-volatile: lets ptxas schedule MMAs around independent ldmatrix issues.
__device__ __forceinline__ void mma_16816(float* d, const uint32_t* a, const uint32_t* b) {
    asm("mma.sync.aligned.m16n8k16.row.col.f32.bf16.bf16.f32 "
        "{%0,%1,%2,%3}, {%4,%5,%6,%7}, {%8,%9}, {%0,%1,%2,%3};"
        : "+f"(d[0]), "+f"(d[1]), "+f"(d[2]), "+f"(d[3])
        : "r"(a[0]), "r"(a[1]), "r"(a[2]), "r"(a[3]), "r"(b[0]), "r"(b[1]));
}
#define CP_ASYNC16(dst, src) \
    asm volatile("cp.async.cg.shared.global [%0], [%1], 16;" :: "r"(dst), "l"(src))
#define CP_COMMIT() asm volatile("cp.async.commit_group;" ::: "memory")
#define CP_WAIT1()  asm volatile("cp.async.wait_group 1;" ::: "memory")
#define CP_WAIT0()  asm volatile("cp.async.wait_group 0;" ::: "memory")

__global__ __launch_bounds__(256, 2)
void score_gemm_mma(const float* __restrict__ Kq, const float* __restrict__ Kt,
                    float* __restrict__ score_global) {
    extern __shared__ char smem[];
    const uint32_t sbase = smem_u32(smem);

    const int tid  = threadIdx.x;
    const int wid  = tid >> 5, lane = tid & 31;
    const int wm   = wid >> 2;          // 0..1 (64 rows)
    const int wn   = wid & 3;           // 0..3 (32 cols)
    const int m0   = blockIdx.y * 128, n0 = blockIdx.x * 128;

    const int lg   = lane >> 3;
    const int lrow = (lane & 7) + (lg & 1) * 8;
    const int lkc  = lg >> 1;

    uint32_t aoff[4][2], boff[2][2];
    #pragma unroll
    for (int mf = 0; mf < 4; mf++)
        #pragma unroll
        for (int s = 0; s < 2; s++)
            aoff[mf][s] = swz(wm * 64 + mf * 16 + lrow, s * 2 + lkc);
    #pragma unroll
    for (int pr = 0; pr < 2; pr++)
        #pragma unroll
        for (int s = 0; s < 2; s++)
            boff[pr][s] = swz(wn * 32 + pr * 16 + lrow, s * 2 + lkc);

    float acc[4][4][4];
    #pragma unroll
    for (int i = 0; i < 4; i++)
        #pragma unroll
        for (int j = 0; j < 4; j++)
            #pragma unroll
            for (int r = 0; r < 4; r++) acc[i][j][r] = 0.0f;

    const int srow = tid >> 1;
    const int ch0  = (tid & 1) * 2;
    uint32_t stoff[2];
    stoff[0] = swz(srow, ch0);
    stoff[1] = swz(srow, ch0 + 1);
    const size_t gaRow = (size_t)(m0 + srow) * 256 + ch0 * 8;
    const size_t gbRow = (size_t)(n0 + srow) * 256 + ch0 * 8;

    #define PREFETCH(kc, st) do {                                              \
        const uint32_t sb = sbase + (uint32_t)((st) * STG);                    \
        const size_t gk = (size_t)(kc) * 32;                                   \
        _Pragma("unroll")                                                      \
        for (int c = 0; c < 2; c++) {                                          \
            CP_ASYNC16(sb + A_HI + stoff[c], g_qhi + gaRow + gk + c * 8);      \
            CP_ASYNC16(sb + A_LO + stoff[c], g_qlo + gaRow + gk + c * 8);      \
            CP_ASYNC16(sb + B_HI + stoff[c], g_thi + gbRow + gk + c * 8);      \
            CP_ASYNC16(sb + B_LO + stoff[c], g_tlo + gbRow + gk + c * 8);      \
        }                                                                      \
        CP_COMMIT();                                                           \
    } while (0)

    PREFETCH(0, 0);
    PREFETCH(1, 1);

    #pragma unroll
    for (int kc = 0; kc < 8; kc++) {
        const int cur = kc % 3;
        if (kc < 7) CP_WAIT1(); else CP_WAIT0();
        __syncthreads();
        if (kc < 6) PREFETCH(kc + 2, (kc + 2) % 3);

        const uint32_t so = sbase + (uint32_t)(cur * STG);
        #pragma unroll
        for (int s = 0; s < 2; s++) {
            // ---- load ah, bh, bl up front (32 frag regs peak, as R8) ----
            uint32_t ah[4][4];
            #pragma unroll
            for (int mf = 0; mf < 4; mf++)
                ldmatrix_x4(ah[mf], so + A_HI + aoff[mf][s]);
            uint32_t bh01[4], bh23[4];
            ldmatrix_x4(bh01, so + B_HI + boff[0][s]);
            ldmatrix_x4(bh23, so + B_HI + boff[1][s]);
            uint32_t bl01[4], bl23[4];
            ldmatrix_x4(bl01, so + B_LO + boff[0][s]);
            ldmatrix_x4(bl23, so + B_LO + boff[1][s]);
            uint32_t bh[4][2] = {{bh01[0], bh01[2]}, {bh01[1], bh01[3]},
                                 {bh23[0], bh23[2]}, {bh23[1], bh23[3]}};
            uint32_t bl[4][2] = {{bl01[0], bl01[2]}, {bl01[1], bl01[3]},
                                 {bl23[0], bl23[2]}, {bl23[1], bl23[3]}};

            // hi * hi
            #pragma unroll
            for (int mf = 0; mf < 4; mf++)
                #pragma unroll
                for (int nf = 0; nf < 4; nf++)
                    mma_16816(acc[mf][nf], ah[mf], bh[nf]);

            // hi * lo (ah, bl) — ah dies after this block
            #pragma unroll
            for (int mf = 0; mf < 4; mf++)
                #pragma unroll
                for (int nf = 0; nf < 4; nf++)
                    mma_16816(acc[mf][nf], ah[mf], bl[nf]);

            // lo * hi (al, bh) — al loads can overlap the hi*lo MMAs
            {
                uint32_t al[4][4];
                #pragma unroll
                for (int mf = 0; mf < 4; mf++)
                    ldmatrix_x4(al[mf], so + A_LO + aoff[mf][s]);
                #pragma unroll
                for (int mf = 0; mf < 4; mf++)
                    #pragma unroll
                    for (int nf = 0; nf < 4; nf++)
                        mma_16816(acc[mf][nf], al[mf], bh[nf]);
            }
        }
    }

    // ---------------- epilogue ----------------
    float at[8], ktv[8], pt[8];
    #pragma unroll
    for (int nf = 0; nf < 4; nf++)
        #pragma unroll
        for (int rb = 0; rb < 2; rb++) {
            int col = n0 + wn * 32 + nf * 8 + (lane & 3) * 2 + rb;
            at[nf * 2 + rb]  = g_At[col];
            ktv[nf * 2 + rb] = fmaxf(Kt[col], 1e-6f);
            pt[nf * 2 + rb]  = g_Pt[col];
        }

    float part[2] = {0.0f, 0.0f};
    #pragma unroll
    for (int mf = 0; mf < 4; mf++) {
        #pragma unroll
        for (int rh = 0; rh < 2; rh++) {
            int row = m0 + wm * 64 + mf * 16 + (lane >> 2) + rh * 8;
            float aq = g_Aq[row];
            float kq = fmaxf(Kq[row], 1e-6f);
            float pq = g_Pq[row];
            float tw = g_tw[row];
            float mx = -1e30f;
            #pragma unroll
            for (int nf = 0; nf < 4; nf++)
                #pragma unroll
                for (int rb = 0; rb < 2; rb++) {
                    int cj = nf * 2 + rb;
                    float beta = 0.5f * (aq * ktv[cj] + at[cj] * kq);
                    float s = fmaf(beta, acc[mf][nf][rh * 2 + rb], -0.5f * (pq + pt[cj]));
                    mx = fmaxf(mx, s);
                }
            mx = fmaxf(mx, __shfl_xor_sync(0xffffffffu, mx, 1));
            mx = fmaxf(mx, __shfl_xor_sync(0xffffffffu, mx, 2));
            part[mf >> 1] += tw * mx;
        }
    }
    #pragma unroll
    for (int g = 0; g < 2; g++) {
        float v = part[g];
        v += __shfl_xor_sync(0xffffffffu, v, 4);
        v += __shfl_xor_sync(0xffffffffu, v, 8);
        v += __shfl_xor_sync(0xffffffffu, v, 16);
        if (lane == 0)
            score_global[(m0 / 32 + wm * 2 + g) * 128 + n0 / 32 + wn] = v;
    }
}

// ---------------------------------------------------------------------------
// Kernel C: logits = score/temp, per-row logsumexp, fused loss (atomicAdd).
// ---------------------------------------------------------------------------
__global__ void softmax_loss_kernel(const float* __restrict__ score,
                                    const float* __restrict__ temp,
                                    float* __restrict__ logits,
                                    float* __restrict__ out_loss) {
    __shared__ float red[4];
    __shared__ float red2[4];
    __shared__ float diag;
    int row = blockIdx.x, t = threadIdx.x;
    float tv = fmaxf(temp[0], 1e-6f);
    float v = score[row * 128 + t] / tv;
    logits[row * 128 + t] = v;
    if (t == row) diag = v;

    float m = v;
    #pragma unroll
    for (int o = 16; o; o >>= 1) m = fmaxf(m, __shfl_xor_sync(0xffffffffu, m, o));
    if ((t & 31) == 0) red[t >> 5] = m;
    __syncthreads();
    m = fmaxf(fmaxf(red[0], red[1]), fmaxf(red[2], red[3]));

    float e = expf(v - m);
    float s = e;
    #pragma unroll
    for (int o = 16; o; o >>= 1) s += __shfl_xor_sync(0xffffffffu, s, o);
    if ((t & 31) == 0) red2[t >> 5] = s;
    __syncthreads();
    if (t == 0) {
        s = red2[0] + red2[1] + red2[2] + red2[3];
        float lse = m + logf(s);
        atomicAdd(out_loss, (lse - diag) * (1.0f / 128.0f));
    }
}

// ---------------------------------------------------------------------------
// Outputs: [0] loss, [1..16385) logits(128x128), then score(128x128), entropy(128x32)
// ---------------------------------------------------------------------------
extern "C" void kernel_launch(void* const* d_in, const int* in_sizes, int n_in,
                              void* d_out, int out_size) {
    const float* q    = (const float*)d_in[0];
    const float* kq   = (const float*)d_in[1];
    const float* t    = (const float*)d_in[2];
    const float* kt   = (const float*)d_in[3];
    const float* temp = (const float*)d_in[4];

    float* out         = (float*)d_out;
    float* out_loss    = out;
    float* out_logits  = out + 1;
    float* out_score   = out + 1 + 128 * 128;
    float* out_entropy = out + 1 + 2 * 128 * 128;

    static int smem_set = 0;
    if (!smem_set) {
        cudaFuncSetAttribute(score_gemm_mma, cudaFuncAttributeMaxDynamicSharedMemorySize, GEMM_SMEM);
        smem_set = 1;
    }

    prep_kernel<<<512, 1024>>>(q, t, kq, kt, out_entropy, out_loss);

    dim3 grid(32, 32);
    score_gemm_mma<<<grid, 256, GEMM_SMEM>>>(kq, kt, out_score);

    softmax_loss_kernel<<<128, 128>>>(out_score, temp, out_logits, out_loss);
}

// round 15
// speedup vs baseline: 1.5349x; 1.3333x over previous
#include <cuda_runtime.h>
#include <cuda_bf16.h>
#include <math.h>
#include <stdint.h>

#define NTOK 4096
#define NB   128

// ---------------------------------------------------------------------------
// Scratch (__device__ globals; no allocation allowed)
// ---------------------------------------------------------------------------
__device__ float g_Aq[NTOK], g_Pq[NTOK], g_At[NTOK], g_Pt[NTOK], g_tw[NTOK];
__device__ __align__(16) __nv_bfloat16 g_qhi[NTOK * 256];
__device__ __align__(16) __nv_bfloat16 g_qlo[NTOK * 256];
__device__ __align__(16) __nv_bfloat16 g_thi[NTOK * 256];

__device__ __forceinline__ uint32_t smem_u32(const void* p) {
    uint32_t a;
    asm("{ .reg .u64 t; cvta.to.shared.u64 t, %1; cvt.u32.u64 %0, t; }" : "=r"(a) : "l"(p));
    return a;
}

// ---------------------------------------------------------------------------
// Kernel A (prep), 1024 threads/block, 512 blocks:
//   blocks [0,256):   it=0 -> q fp32->bf16 hi+lo split; it=1 -> t hi only
//   blocks [256,384): q-token Bessel stats (one token per warp) + token weights
//   blocks [384,512): t-token Bessel stats
// Also zeroes the loss accumulator.
// ---------------------------------------------------------------------------
__global__ __launch_bounds__(1024)
void prep_kernel(const float* __restrict__ q, const float* __restrict__ t,
                 const float* __restrict__ kq, const float* __restrict__ kt,
                 float* __restrict__ entropy_out, float* __restrict__ out_loss) {
    const int blk = blockIdx.x, tid = threadIdx.x;
    if (blk == 0 && tid == 0) out_loss[0] = 0.0f;

    if (blk < 256) {
        // it = 0: q (hi + lo); it = 1: t (hi only)
        {
            int j = blk * 1024 + tid;                 // q float4 index
            float4 v = ((const float4*)q)[j];
            float x[4] = {v.x, v.y, v.z, v.w};
            uint32_t hi2[2], lo2[2];
            #pragma unroll
            for (int p = 0; p < 2; p++) {
                __nv_bfloat16 h0 = __float2bfloat16(x[p * 2]);
                __nv_bfloat16 h1 = __float2bfloat16(x[p * 2 + 1]);
                __nv_bfloat16 l0 = __float2bfloat16(x[p * 2] - __bfloat162float(h0));
                __nv_bfloat16 l1 = __float2bfloat16(x[p * 2 + 1] - __bfloat162float(h1));
                hi2[p] = (uint32_t)__bfloat16_as_ushort(h0) | ((uint32_t)__bfloat16_as_ushort(h1) << 16);
                lo2[p] = (uint32_t)__bfloat16_as_ushort(l0) | ((uint32_t)__bfloat16_as_ushort(l1) << 16);
            }
            ((uint2*)g_qhi)[j] = make_uint2(hi2[0], hi2[1]);
            ((uint2*)g_qlo)[j] = make_uint2(lo2[0], lo2[1]);
        }
        {
            int j = blk * 1024 + tid;                 // t float4 index
            float4 v = ((const float4*)t)[j];
            float x[4] = {v.x, v.y, v.z, v.w};
            uint32_t hi2[2];
            #pragma unroll
            for (int p = 0; p < 2; p++) {
                __nv_bfloat16 h0 = __float2bfloat16(x[p * 2]);
                __nv_bfloat16 h1 = __float2bfloat16(x[p * 2 + 1]);
                hi2[p] = (uint32_t)__bfloat16_as_ushort(h0) | ((uint32_t)__bfloat16_as_ushort(h1) << 16);
            }
            ((uint2*)g_thi)[j] = make_uint2(hi2[0], hi2[1]);
        }
        return;
    }

    __shared__ float s_csum[50];
    __shared__ float s_lk[50];
    __shared__ float s_ent[32];

    if (tid < 50) {
        s_csum[tid] = lgammaf((float)(tid + 1)) + lgammaf((float)(tid + 128));
        s_lk[tid]   = logf((float)(tid + 128));
    }
    __syncthreads();

    const int warp = tid >> 5, lane = tid & 31;
    const bool isq = blk < 384;
    const int j = isq ? (blk - 256) * 32 + warp : (blk - 384) * 32 + warp;

    float x = fmaxf((isq ? kq : kt)[j], 1e-6f);
    float L = logf(0.5f * x);

    float t1a = fmaf(2.0f * lane + 127.0f, L, -s_csum[lane]);
    float t2a = t1a + L - s_lk[lane];
    float t1b = -1e30f, t2b = -1e30f;
    if (lane < 18) {
        int k2 = lane + 32;
        t1b = fmaf(2.0f * k2 + 127.0f, L, -s_csum[k2]);
        t2b = t1b + L - s_lk[k2];
    }
    float m1 = fmaxf(t1a, t1b), m2 = fmaxf(t2a, t2b);
    #pragma unroll
    for (int o = 16; o; o >>= 1) {
        m1 = fmaxf(m1, __shfl_xor_sync(0xffffffffu, m1, o));
        m2 = fmaxf(m2, __shfl_xor_sync(0xffffffffu, m2, o));
    }
    float s1 = __expf(t1a - m1) + (lane < 18 ? __expf(t1b - m1) : 0.0f);
    float s2 = __expf(t2a - m2) + (lane < 18 ? __expf(t2b - m2) : 0.0f);
    #pragma unroll
    for (int o = 16; o; o >>= 1) {
        s1 += __shfl_xor_sync(0xffffffffu, s1, o);
        s2 += __shfl_xor_sync(0xffffffffu, s2, o);
    }
    float lb127 = m1 + logf(s1);
    float lb128 = m2 + logf(s2);
    float diff = fminf(fmaxf(lb128 - lb127, -60.0f), 0.0f);
    float A = fminf(fmaxf(expf(diff), 1e-8f), 1.0f - 1e-6f);

    if (isq) {
        if (lane == 0) {
            g_Aq[j] = A;
            g_Pq[j] = A * x;
            float logC = 127.0f * logf(x) - (128.0f * 1.8378770664093454f) - lb127;
            float ent = -logC - x * A;
            entropy_out[j] = ent;
            s_ent[warp] = ent;
        }
        __syncthreads();
        if (tid < 32) {
            float xe = -2.0f * s_ent[tid];
            float m = xe;
            #pragma unroll
            for (int o = 16; o; o >>= 1) m = fmaxf(m, __shfl_xor_sync(0xffffffffu, m, o));
            float e = expf(xe - m);
            float s = e;
            #pragma unroll
            for (int o = 16; o; o >>= 1) s += __shfl_xor_sync(0xffffffffu, s, o);
            g_tw[(blk - 256) * 32 + tid] = e / s;
        }
    } else if (lane == 0) {
        g_At[j] = A;
        g_Pt[j] = A * x;
    }
}

// ---------------------------------------------------------------------------
// Kernel B: ASYMMETRIC split-bf16 mma.sync GEMM:
//   sim = (a_hi + a_lo) . b_hi  -> TWO products (hi*hi + lo*hi).
// Dropped a.b_lo term: RMS sim err ~1e-4, beta<=~10 -> rel_err ~1e-4 << 1e-3.
// Pipeline: R8-proven 3-stage cp.async, BK=32, one sync per chunk, +2
// lookahead. CTA tile 128x128, 8 warps (2x4), warp tile 64x32, 2 CTA/SM,
// fused score epilogue. Stage = A_hi 8K + A_lo 8K + B_hi 8K = 24KB.
// ---------------------------------------------------------------------------
#define STG   24576
#define A_HI  0
#define A_LO  8192
#define B_HI  16384
#define GEMM_SMEM (3 * STG)

__device__ __forceinline__ uint32_t swz(int r, int c) {
    return (uint32_t)(((r >> 1) * 128) + (((((r & 1) << 2) | c) ^ ((r >> 1) & 7)) << 4));
}
__device__ __forceinline__ void ldmatrix_x4(uint32_t* r, uint32_t addr) {
    asm volatile("ldmatrix.sync.aligned.m8n8.x4.shared.b16 {%0,%1,%2,%3}, [%4];"
                 : "=r"(r[0]), "=r"(r[1]), "=r"(r[2]), "=r"(r[3]) : "r"(addr));
}
__device__ __forceinline__ void mma_16816(float* d, const uint32_t* a, const uint32_t* b) {
    asm("mma.sync.aligned.m16n8k16.row.col.f32.bf16.bf16.f32 "
        "{%0,%1,%2,%3}, {%4,%5,%6,%7}, {%8,%9}, {%0,%1,%2,%3};"
        : "+f"(d[0]), "+f"(d[1]), "+f"(d[2]), "+f"(d[3])
        : "r"(a[0]), "r"(a[1]), "r"(a[2]), "r"(a[3]), "r"(b[0]), "r"(b[1]));
}
#define CP_ASYNC16(dst, src) \
    asm volatile("cp.async.cg.shared.global [%0], [%1], 16;" :: "r"(dst), "l"(src))
#define CP_COMMIT() asm volatile("cp.async.commit_group;" ::: "memory")
#define CP_WAIT1()  asm volatile("cp.async.wait_group 1;" ::: "memory")
#define CP_WAIT0()  asm volatile("cp.async.wait_group 0;" ::: "memory")

__global__ __launch_bounds__(256, 2)
void score_gemm_mma(const float* __restrict__ Kq, const float* __restrict__ Kt,
                    float* __restrict__ score_global) {
    extern __shared__ char smem[];
    const uint32_t sbase = smem_u32(smem);

    const int tid  = threadIdx.x;
    const int wid  = tid >> 5, lane = tid & 31;
    const int wm   = wid >> 2;          // 0..1 (64 rows)
    const int wn   = wid & 3;           // 0..3 (32 cols)
    const int m0   = blockIdx.y * 128, n0 = blockIdx.x * 128;

    const int lg   = lane >> 3;
    const int lrow = (lane & 7) + (lg & 1) * 8;
    const int lkc  = lg >> 1;

    uint32_t aoff[4][2], boff[2][2];
    #pragma unroll
    for (int mf = 0; mf < 4; mf++)
        #pragma unroll
        for (int s = 0; s < 2; s++)
            aoff[mf][s] = swz(wm * 64 + mf * 16 + lrow, s * 2 + lkc);
    #pragma unroll
    for (int pr = 0; pr < 2; pr++)
        #pragma unroll
        for (int s = 0; s < 2; s++)
            boff[pr][s] = swz(wn * 32 + pr * 16 + lrow, s * 2 + lkc);

    float acc[4][4][4];
    #pragma unroll
    for (int i = 0; i < 4; i++)
        #pragma unroll
        for (int j = 0; j < 4; j++)
            #pragma unroll
            for (int r = 0; r < 4; r++) acc[i][j][r] = 0.0f;

    const int srow = tid >> 1;
    const int ch0  = (tid & 1) * 2;
    uint32_t stoff[2];
    stoff[0] = swz(srow, ch0);
    stoff[1] = swz(srow, ch0 + 1);
    const size_t gaRow = (size_t)(m0 + srow) * 256 + ch0 * 8;
    const size_t gbRow = (size_t)(n0 + srow) * 256 + ch0 * 8;

    #define PREFETCH(kc, st) do {                                              \
        const uint32_t sb = sbase + (uint32_t)((st) * STG);                    \
        const size_t gk = (size_t)(kc) * 32;                                   \
        _Pragma("unroll")                                                      \
        for (int c = 0; c < 2; c++) {                                          \
            CP_ASYNC16(sb + A_HI + stoff[c], g_qhi + gaRow + gk + c * 8);      \
            CP_ASYNC16(sb + A_LO + stoff[c], g_qlo + gaRow + gk + c * 8);      \
            CP_ASYNC16(sb + B_HI + stoff[c], g_thi + gbRow + gk + c * 8);      \
        }                                                                      \
        CP_COMMIT();                                                           \
    } while (0)

    PREFETCH(0, 0);
    PREFETCH(1, 1);

    #pragma unroll
    for (int kc = 0; kc < 8; kc++) {
        const int cur = kc % 3;
        if (kc < 7) CP_WAIT1(); else CP_WAIT0();
        __syncthreads();
        if (kc < 6) PREFETCH(kc + 2, (kc + 2) % 3);

        const uint32_t so = sbase + (uint32_t)(cur * STG);
        #pragma unroll
        for (int s = 0; s < 2; s++) {
            uint32_t ah[4][4];
            #pragma unroll
            for (int mf = 0; mf < 4; mf++)
                ldmatrix_x4(ah[mf], so + A_HI + aoff[mf][s]);
            uint32_t bh01[4], bh23[4];
            ldmatrix_x4(bh01, so + B_HI + boff[0][s]);
            ldmatrix_x4(bh23, so + B_HI + boff[1][s]);
            uint32_t bh[4][2] = {{bh01[0], bh01[2]}, {bh01[1], bh01[3]},
                                 {bh23[0], bh23[2]}, {bh23[1], bh23[3]}};

            // hi * hi
            #pragma unroll
            for (int mf = 0; mf < 4; mf++)
                #pragma unroll
                for (int nf = 0; nf < 4; nf++)
                    mma_16816(acc[mf][nf], ah[mf], bh[nf]);

            // lo * hi (al loads overlap hi*hi MMAs via scoreboarding)
            {
                uint32_t al[4][4];
                #pragma unroll
                for (int mf = 0; mf < 4; mf++)
                    ldmatrix_x4(al[mf], so + A_LO + aoff[mf][s]);
                #pragma unroll
                for (int mf = 0; mf < 4; mf++)
                    #pragma unroll
                    for (int nf = 0; nf < 4; nf++)
                        mma_16816(acc[mf][nf], al[mf], bh[nf]);
            }
        }
    }

    // ---------------- epilogue ----------------
    float at[8], ktv[8], pt[8];
    #pragma unroll
    for (int nf = 0; nf < 4; nf++)
        #pragma unroll
        for (int rb = 0; rb < 2; rb++) {
            int col = n0 + wn * 32 + nf * 8 + (lane & 3) * 2 + rb;
            at[nf * 2 + rb]  = g_At[col];
            ktv[nf * 2 + rb] = fmaxf(Kt[col], 1e-6f);
            pt[nf * 2 + rb]  = g_Pt[col];
        }

    float part[2] = {0.0f, 0.0f};
    #pragma unroll
    for (int mf = 0; mf < 4; mf++) {
        #pragma unroll
        for (int rh = 0; rh < 2; rh++) {
            int row = m0 + wm * 64 + mf * 16 + (lane >> 2) + rh * 8;
            float aq = g_Aq[row];
            float kq = fmaxf(Kq[row], 1e-6f);
            float pq = g_Pq[row];
            float tw = g_tw[row];
            float mx = -1e30f;
            #pragma unroll
            for (int nf = 0; nf < 4; nf++)
                #pragma unroll
                for (int rb = 0; rb < 2; rb++) {
                    int cj = nf * 2 + rb;
                    float beta = 0.5f * (aq * ktv[cj] + at[cj] * kq);
                    float s = fmaf(beta, acc[mf][nf][rh * 2 + rb], -0.5f * (pq + pt[cj]));
                    mx = fmaxf(mx, s);
                }
            mx = fmaxf(mx, __shfl_xor_sync(0xffffffffu, mx, 1));
            mx = fmaxf(mx, __shfl_xor_sync(0xffffffffu, mx, 2));
            part[mf >> 1] += tw * mx;
        }
    }
    #pragma unroll
    for (int g = 0; g < 2; g++) {
        float v = part[g];
        v += __shfl_xor_sync(0xffffffffu, v, 4);
        v += __shfl_xor_sync(0xffffffffu, v, 8);
        v += __shfl_xor_sync(0xffffffffu, v, 16);
        if (lane == 0)
            score_global[(m0 / 32 + wm * 2 + g) * 128 + n0 / 32 + wn] = v;
    }
}

// ---------------------------------------------------------------------------
// Kernel C: logits = score/temp, per-row logsumexp, fused loss (atomicAdd).
// ---------------------------------------------------------------------------
__global__ void softmax_loss_kernel(const float* __restrict__ score,
                                    const float* __restrict__ temp,
                                    float* __restrict__ logits,
                                    float* __restrict__ out_loss) {
    __shared__ float red[4];
    __shared__ float red2[4];
    __shared__ float diag;
    int row = blockIdx.x, t = threadIdx.x;
    float tv = fmaxf(temp[0], 1e-6f);
    float v = score[row * 128 + t] / tv;
    logits[row * 128 + t] = v;
    if (t == row) diag = v;

    float m = v;
    #pragma unroll
    for (int o = 16; o; o >>= 1) m = fmaxf(m, __shfl_xor_sync(0xffffffffu, m, o));
    if ((t & 31) == 0) red[t >> 5] = m;
    __syncthreads();
    m = fmaxf(fmaxf(red[0], red[1]), fmaxf(red[2], red[3]));

    float e = expf(v - m);
    float s = e;
    #pragma unroll
    for (int o = 16; o; o >>= 1) s += __shfl_xor_sync(0xffffffffu, s, o);
    if ((t & 31) == 0) red2[t >> 5] = s;
    __syncthreads();
    if (t == 0) {
        s = red2[0] + red2[1] + red2[2] + red2[3];
        float lse = m + logf(s);
        atomicAdd(out_loss, (lse - diag) * (1.0f / 128.0f));
    }
}

// ---------------------------------------------------------------------------
// Outputs: [0] loss, [1..16385) logits(128x128), then score(128x128), entropy(128x32)
// ---------------------------------------------------------------------------
extern "C" void kernel_launch(void* const* d_in, const int* in_sizes, int n_in,
                              void* d_out, int out_size) {
    const float* q    = (const float*)d_in[0];
    const float* kq   = (const float*)d_in[1];
    const float* t    = (const float*)d_in[2];
    const float* kt   = (const float*)d_in[3];
    const float* temp = (const float*)d_in[4];

    float* out         = (float*)d_out;
    float* out_loss    = out;
    float* out_logits  = out + 1;
    float* out_score   = out + 1 + 128 * 128;
    float* out_entropy = out + 1 + 2 * 128 * 128;

    static int smem_set = 0;
    if (!smem_set) {
        cudaFuncSetAttribute(score_gemm_mma, cudaFuncAttributeMaxDynamicSharedMemorySize, GEMM_SMEM);
        smem_set = 1;
    }

    prep_kernel<<<512, 1024>>>(q, t, kq, kt, out_entropy, out_loss);

    dim3 grid(32, 32);
    score_gemm_mma<<<grid, 256, GEMM_SMEM>>>(kq, kt, out_score);

    softmax_loss_kernel<<<128, 128>>>(out_score, temp, out_logits, out_loss);
}

// round 16
// speedup vs baseline: 1.6189x; 1.0547x over previous
#include <cuda_runtime.h>
#include <cuda_bf16.h>
#include <math.h>
#include <stdint.h>

#define NTOK 4096
#define NB   128

// ---------------------------------------------------------------------------
// Scratch (__device__ globals; no allocation allowed)
// ---------------------------------------------------------------------------
__device__ float g_Aq[NTOK], g_Pq[NTOK], g_At[NTOK], g_Pt[NTOK], g_tw[NTOK];
__device__ __align__(16) __nv_bfloat16 g_qhi[NTOK * 256];
__device__ __align__(16) __nv_bfloat16 g_thi[NTOK * 256];

__device__ __forceinline__ uint32_t smem_u32(const void* p) {
    uint32_t a;
    asm("{ .reg .u64 t; cvta.to.shared.u64 t, %1; cvt.u32.u64 %0, t; }" : "=r"(a) : "l"(p));
    return a;
}

// ---------------------------------------------------------------------------
// Kernel A (prep), 1024 threads/block, 512 blocks:
//   blocks [0,256):   fp32->bf16 (hi only) for q and t (2 float4/thread)
//   blocks [256,384): q-token Bessel stats (one token per warp) + token weights
//   blocks [384,512): t-token Bessel stats
// Also zeroes the loss accumulator.
// ---------------------------------------------------------------------------
__global__ __launch_bounds__(1024)
void prep_kernel(const float* __restrict__ q, const float* __restrict__ t,
                 const float* __restrict__ kq, const float* __restrict__ kt,
                 float* __restrict__ entropy_out, float* __restrict__ out_loss) {
    const int blk = blockIdx.x, tid = threadIdx.x;
    if (blk == 0 && tid == 0) out_loss[0] = 0.0f;

    if (blk < 256) {
        #pragma unroll
        for (int it = 0; it < 2; it++) {
            int i = blk * 1024 + tid + it * 262144;   // float4 index 0..524287
            bool is_q = i < 262144;
            int j = is_q ? i : i - 262144;
            float4 v = ((const float4*)(is_q ? q : t))[j];
            float x[4] = {v.x, v.y, v.z, v.w};
            uint32_t hi2[2];
            #pragma unroll
            for (int p = 0; p < 2; p++) {
                __nv_bfloat16 h0 = __float2bfloat16(x[p * 2]);
                __nv_bfloat16 h1 = __float2bfloat16(x[p * 2 + 1]);
                hi2[p] = (uint32_t)__bfloat16_as_ushort(h0) | ((uint32_t)__bfloat16_as_ushort(h1) << 16);
            }
            ((uint2*)(is_q ? g_qhi : g_thi))[j] = make_uint2(hi2[0], hi2[1]);
        }
        return;
    }

    __shared__ float s_csum[50];
    __shared__ float s_lk[50];
    __shared__ float s_ent[32];

    if (tid < 50) {
        s_csum[tid] = lgammaf((float)(tid + 1)) + lgammaf((float)(tid + 128));
        s_lk[tid]   = logf((float)(tid + 128));
    }
    __syncthreads();

    const int warp = tid >> 5, lane = tid & 31;
    const bool isq = blk < 384;
    const int j = isq ? (blk - 256) * 32 + warp : (blk - 384) * 32 + warp;

    float x = fmaxf((isq ? kq : kt)[j], 1e-6f);
    float L = logf(0.5f * x);

    float t1a = fmaf(2.0f * lane + 127.0f, L, -s_csum[lane]);
    float t2a = t1a + L - s_lk[lane];
    float t1b = -1e30f, t2b = -1e30f;
    if (lane < 18) {
        int k2 = lane + 32;
        t1b = fmaf(2.0f * k2 + 127.0f, L, -s_csum[k2]);
        t2b = t1b + L - s_lk[k2];
    }
    float m1 = fmaxf(t1a, t1b), m2 = fmaxf(t2a, t2b);
    #pragma unroll
    for (int o = 16; o; o >>= 1) {
        m1 = fmaxf(m1, __shfl_xor_sync(0xffffffffu, m1, o));
        m2 = fmaxf(m2, __shfl_xor_sync(0xffffffffu, m2, o));
    }
    float s1 = __expf(t1a - m1) + (lane < 18 ? __expf(t1b - m1) : 0.0f);
    float s2 = __expf(t2a - m2) + (lane < 18 ? __expf(t2b - m2) : 0.0f);
    #pragma unroll
    for (int o = 16; o; o >>= 1) {
        s1 += __shfl_xor_sync(0xffffffffu, s1, o);
        s2 += __shfl_xor_sync(0xffffffffu, s2, o);
    }
    float lb127 = m1 + logf(s1);
    float lb128 = m2 + logf(s2);
    float diff = fminf(fmaxf(lb128 - lb127, -60.0f), 0.0f);
    float A = fminf(fmaxf(expf(diff), 1e-8f), 1.0f - 1e-6f);

    if (isq) {
        if (lane == 0) {
            g_Aq[j] = A;
            g_Pq[j] = A * x;
            float logC = 127.0f * logf(x) - (128.0f * 1.8378770664093454f) - lb127;
            float ent = -logC - x * A;
            entropy_out[j] = ent;
            s_ent[warp] = ent;
        }
        __syncthreads();
        if (tid < 32) {
            float xe = -2.0f * s_ent[tid];
            float m = xe;
            #pragma unroll
            for (int o = 16; o; o >>= 1) m = fmaxf(m, __shfl_xor_sync(0xffffffffu, m, o));
            float e = expf(xe - m);
            float s = e;
            #pragma unroll
            for (int o = 16; o; o >>= 1) s += __shfl_xor_sync(0xffffffffu, s, o);
            g_tw[(blk - 256) * 32 + tid] = e / s;
        }
    } else if (lane == 0) {
        g_At[j] = A;
        g_Pt[j] = A * x;
    }
}

// ---------------------------------------------------------------------------
// Kernel B: SINGLE-product bf16 mma.sync GEMM: sim ~= a_hi . b_hi.
// Error model (grounded in R15 measurement): dropped a.delta_b gave 2.6e-5;
// symmetric delta_a.b adds in quadrature -> ~4e-5 total, 25x under 1e-3.
// Pipeline: proven 3-stage cp.async, BK=32, one sync per chunk, +2 lookahead.
// CTA tile 128x128, 8 warps (2x4), warp tile 64x32, 2 CTA/SM, fused epilogue.
// Stage = A_hi 8K + B_hi 8K = 16KB; 3 stages = 48KB.
// ---------------------------------------------------------------------------
#define STG   16384
#define A_HI  0
#define B_HI  8192
#define GEMM_SMEM (3 * STG)

__device__ __forceinline__ uint32_t swz(int r, int c) {
    return (uint32_t)(((r >> 1) * 128) + (((((r & 1) << 2) | c) ^ ((r >> 1) & 7)) << 4));
}
__device__ __forceinline__ void ldmatrix_x4(uint32_t* r, uint32_t addr) {
    asm volatile("ldmatrix.sync.aligned.m8n8.x4.shared.b16 {%0,%1,%2,%3}, [%4];"
                 : "=r"(r[0]), "=r"(r[1]), "=r"(r[2]), "=r"(r[3]) : "r"(addr));
}
__device__ __forceinline__ void mma_16816(float* d, const uint32_t* a, const uint32_t* b) {
    asm("mma.sync.aligned.m16n8k16.row.col.f32.bf16.bf16.f32 "
        "{%0,%1,%2,%3}, {%4,%5,%6,%7}, {%8,%9}, {%0,%1,%2,%3};"
        : "+f"(d[0]), "+f"(d[1]), "+f"(d[2]), "+f"(d[3])
        : "r"(a[0]), "r"(a[1]), "r"(a[2]), "r"(a[3]), "r"(b[0]), "r"(b[1]));
}
#define CP_ASYNC16(dst, src) \
    asm volatile("cp.async.cg.shared.global [%0], [%1], 16;" :: "r"(dst), "l"(src))
#define CP_COMMIT() asm volatile("cp.async.commit_group;" ::: "memory")
#define CP_WAIT1()  asm volatile("cp.async.wait_group 1;" ::: "memory")
#define CP_WAIT0()  asm volatile("cp.async.wait_group 0;" ::: "memory")

__global__ __launch_bounds__(256, 2)
void score_gemm_mma(const float* __restrict__ Kq, const float* __restrict__ Kt,
                    float* __restrict__ score_global) {
    extern __shared__ char smem[];
    const uint32_t sbase = smem_u32(smem);

    const int tid  = threadIdx.x;
    const int wid  = tid >> 5, lane = tid & 31;
    const int wm   = wid >> 2;          // 0..1 (64 rows)
    const int wn   = wid & 3;           // 0..3 (32 cols)
    const int m0   = blockIdx.y * 128, n0 = blockIdx.x * 128;

    const int lg   = lane >> 3;
    const int lrow = (lane & 7) + (lg & 1) * 8;
    const int lkc  = lg >> 1;

    uint32_t aoff[4][2], boff[2][2];
    #pragma unroll
    for (int mf = 0; mf < 4; mf++)
        #pragma unroll
        for (int s = 0; s < 2; s++)
            aoff[mf][s] = swz(wm * 64 + mf * 16 + lrow, s * 2 + lkc);
    #pragma unroll
    for (int pr = 0; pr < 2; pr++)
        #pragma unroll
        for (int s = 0; s < 2; s++)
            boff[pr][s] = swz(wn * 32 + pr * 16 + lrow, s * 2 + lkc);

    float acc[4][4][4];
    #pragma unroll
    for (int i = 0; i < 4; i++)
        #pragma unroll
        for (int j = 0; j < 4; j++)
            #pragma unroll
            for (int r = 0; r < 4; r++) acc[i][j][r] = 0.0f;

    const int srow = tid >> 1;
    const int ch0  = (tid & 1) * 2;
    uint32_t stoff[2];
    stoff[0] = swz(srow, ch0);
    stoff[1] = swz(srow, ch0 + 1);
    const size_t gaRow = (size_t)(m0 + srow) * 256 + ch0 * 8;
    const size_t gbRow = (size_t)(n0 + srow) * 256 + ch0 * 8;

    #define PREFETCH(kc, st) do {                                              \
        const uint32_t sb = sbase + (uint32_t)((st) * STG);                    \
        const size_t gk = (size_t)(kc) * 32;                                   \
        _Pragma("unroll")                                                      \
        for (int c = 0; c < 2; c++) {                                          \
            CP_ASYNC16(sb + A_HI + stoff[c], g_qhi + gaRow + gk + c * 8);      \
            CP_ASYNC16(sb + B_HI + stoff[c], g_thi + gbRow + gk + c * 8);      \
        }                                                                      \
        CP_COMMIT();                                                           \
    } while (0)

    PREFETCH(0, 0);
    PREFETCH(1, 1);

    #pragma unroll
    for (int kc = 0; kc < 8; kc++) {
        const int cur = kc % 3;
        if (kc < 7) CP_WAIT1(); else CP_WAIT0();
        __syncthreads();
        if (kc < 6) PREFETCH(kc + 2, (kc + 2) % 3);

        const uint32_t so = sbase + (uint32_t)(cur * STG);
        #pragma unroll
        for (int s = 0; s < 2; s++) {
            uint32_t ah[4][4];
            #pragma unroll
            for (int mf = 0; mf < 4; mf++)
                ldmatrix_x4(ah[mf], so + A_HI + aoff[mf][s]);
            uint32_t bh01[4], bh23[4];
            ldmatrix_x4(bh01, so + B_HI + boff[0][s]);
            ldmatrix_x4(bh23, so + B_HI + boff[1][s]);
            uint32_t bh[4][2] = {{bh01[0], bh01[2]}, {bh01[1], bh01[3]},
                                 {bh23[0], bh23[2]}, {bh23[1], bh23[3]}};

            #pragma unroll
            for (int mf = 0; mf < 4; mf++)
                #pragma unroll
                for (int nf = 0; nf < 4; nf++)
                    mma_16816(acc[mf][nf], ah[mf], bh[nf]);
        }
    }

    // ---------------- epilogue ----------------
    float at[8], ktv[8], pt[8];
    #pragma unroll
    for (int nf = 0; nf < 4; nf++)
        #pragma unroll
        for (int rb = 0; rb < 2; rb++) {
            int col = n0 + wn * 32 + nf * 8 + (lane & 3) * 2 + rb;
            at[nf * 2 + rb]  = g_At[col];
            ktv[nf * 2 + rb] = fmaxf(Kt[col], 1e-6f);
            pt[nf * 2 + rb]  = g_Pt[col];
        }

    float part[2] = {0.0f, 0.0f};
    #pragma unroll
    for (int mf = 0; mf < 4; mf++) {
        #pragma unroll
        for (int rh = 0; rh < 2; rh++) {
            int row = m0 + wm * 64 + mf * 16 + (lane >> 2) + rh * 8;
            float aq = g_Aq[row];
            float kq = fmaxf(Kq[row], 1e-6f);
            float pq = g_Pq[row];
            float tw = g_tw[row];
            float mx = -1e30f;
            #pragma unroll
            for (int nf = 0; nf < 4; nf++)
                #pragma unroll
                for (int rb = 0; rb < 2; rb++) {
                    int cj = nf * 2 + rb;
                    float beta = 0.5f * (aq * ktv[cj] + at[cj] * kq);
                    float s = fmaf(beta, acc[mf][nf][rh * 2 + rb], -0.5f * (pq + pt[cj]));
                    mx = fmaxf(mx, s);
                }
            mx = fmaxf(mx, __shfl_xor_sync(0xffffffffu, mx, 1));
            mx = fmaxf(mx, __shfl_xor_sync(0xffffffffu, mx, 2));
            part[mf >> 1] += tw * mx;
        }
    }
    #pragma unroll
    for (int g = 0; g < 2; g++) {
        float v = part[g];
        v += __shfl_xor_sync(0xffffffffu, v, 4);
        v += __shfl_xor_sync(0xffffffffu, v, 8);
        v += __shfl_xor_sync(0xffffffffu, v, 16);
        if (lane == 0)
            score_global[(m0 / 32 + wm * 2 + g) * 128 + n0 / 32 + wn] = v;
    }
}

// ---------------------------------------------------------------------------
// Kernel C: logits = score/temp, per-row logsumexp, fused loss (atomicAdd).
// ---------------------------------------------------------------------------
__global__ void softmax_loss_kernel(const float* __restrict__ score,
                                    const float* __restrict__ temp,
                                    float* __restrict__ logits,
                                    float* __restrict__ out_loss) {
    __shared__ float red[4];
    __shared__ float red2[4];
    __shared__ float diag;
    int row = blockIdx.x, t = threadIdx.x;
    float tv = fmaxf(temp[0], 1e-6f);
    float v = score[row * 128 + t] / tv;
    logits[row * 128 + t] = v;
    if (t == row) diag = v;

    float m = v;
    #pragma unroll
    for (int o = 16; o; o >>= 1) m = fmaxf(m, __shfl_xor_sync(0xffffffffu, m, o));
    if ((t & 31) == 0) red[t >> 5] = m;
    __syncthreads();
    m = fmaxf(fmaxf(red[0], red[1]), fmaxf(red[2], red[3]));

    float e = expf(v - m);
    float s = e;
    #pragma unroll
    for (int o = 16; o; o >>= 1) s += __shfl_xor_sync(0xffffffffu, s, o);
    if ((t & 31) == 0) red2[t >> 5] = s;
    __syncthreads();
    if (t == 0) {
        s = red2[0] + red2[1] + red2[2] + red2[3];
        float lse = m + logf(s);
        atomicAdd(out_loss, (lse - diag) * (1.0f / 128.0f));
    }
}

// ---------------------------------------------------------------------------
// Outputs: [0] loss, [1..16385) logits(128x128), then score(128x128), entropy(128x32)
// ---------------------------------------------------------------------------
extern "C" void kernel_launch(void* const* d_in, const int* in_sizes, int n_in,
                              void* d_out, int out_size) {
    const float* q    = (const float*)d_in[0];
    const float* kq   = (const float*)d_in[1];
    const float* t    = (const float*)d_in[2];
    const float* kt   = (const float*)d_in[3];
    const float* temp = (const float*)d_in[4];

    float* out         = (float*)d_out;
    float* out_loss    = out;
    float* out_logits  = out + 1;
    float* out_score   = out + 1 + 128 * 128;
    float* out_entropy = out + 1 + 2 * 128 * 128;

    static int smem_set = 0;
    if (!smem_set) {
        cudaFuncSetAttribute(score_gemm_mma, cudaFuncAttributeMaxDynamicSharedMemorySize, GEMM_SMEM);
        smem_set = 1;
    }

    prep_kernel<<<512, 1024>>>(q, t, kq, kt, out_entropy, out_loss);

    dim3 grid(32, 32);
    score_gemm_mma<<<grid, 256, GEMM_SMEM>>>(kq, kt, out_score);

    softmax_loss_kernel<<<128, 128>>>(out_score, temp, out_logits, out_loss);
}

// round 17
// speedup vs baseline: 2.2618x; 1.3972x over previous
#include <cuda_runtime.h>
#include <cuda_bf16.h>
#include <math.h>
#include <stdint.h>

#define NTOK 4096
#define NB   128

// ---------------------------------------------------------------------------
// Scratch (__device__ globals; no allocation allowed)
// ---------------------------------------------------------------------------
__device__ float g_Aq[NTOK], g_Pq[NTOK], g_At[NTOK], g_Pt[NTOK], g_tw[NTOK];
__device__ __align__(16) __nv_bfloat16 g_qhi[NTOK * 256];
__device__ __align__(16) __nv_bfloat16 g_thi[NTOK * 256];

__device__ __forceinline__ uint32_t smem_u32(const void* p) {
    uint32_t a;
    asm("{ .reg .u64 t; cvta.to.shared.u64 t, %1; cvt.u32.u64 %0, t; }" : "=r"(a) : "l"(p));
    return a;
}

// ---------------------------------------------------------------------------
// Kernel A (prep), 1024 threads/block, 512 blocks:
//   blocks [0,256):   fp32->bf16 (hi only) for q and t (2 float4/thread)
//   blocks [256,384): q-token Bessel stats (one token per warp) + token weights
//   blocks [384,512): t-token Bessel stats
// Also zeroes the loss accumulator.
// ---------------------------------------------------------------------------
__global__ __launch_bounds__(1024)
void prep_kernel(const float* __restrict__ q, const float* __restrict__ t,
                 const float* __restrict__ kq, const float* __restrict__ kt,
                 float* __restrict__ entropy_out, float* __restrict__ out_loss) {
    const int blk = blockIdx.x, tid = threadIdx.x;
    if (blk == 0 && tid == 0) out_loss[0] = 0.0f;

    if (blk < 256) {
        #pragma unroll
        for (int it = 0; it < 2; it++) {
            int i = blk * 1024 + tid + it * 262144;   // float4 index 0..524287
            bool is_q = i < 262144;
            int j = is_q ? i : i - 262144;
            float4 v = ((const float4*)(is_q ? q : t))[j];
            float x[4] = {v.x, v.y, v.z, v.w};
            uint32_t hi2[2];
            #pragma unroll
            for (int p = 0; p < 2; p++) {
                __nv_bfloat16 h0 = __float2bfloat16(x[p * 2]);
                __nv_bfloat16 h1 = __float2bfloat16(x[p * 2 + 1]);
                hi2[p] = (uint32_t)__bfloat16_as_ushort(h0) | ((uint32_t)__bfloat16_as_ushort(h1) << 16);
            }
            ((uint2*)(is_q ? g_qhi : g_thi))[j] = make_uint2(hi2[0], hi2[1]);
        }
        return;
    }

    __shared__ float s_csum[50];
    __shared__ float s_lk[50];
    __shared__ float s_ent[32];

    if (tid < 50) {
        s_csum[tid] = lgammaf((float)(tid + 1)) + lgammaf((float)(tid + 128));
        s_lk[tid]   = logf((float)(tid + 128));
    }
    __syncthreads();

    const int warp = tid >> 5, lane = tid & 31;
    const bool isq = blk < 384;
    const int j = isq ? (blk - 256) * 32 + warp : (blk - 384) * 32 + warp;

    float x = fmaxf((isq ? kq : kt)[j], 1e-6f);
    float L = logf(0.5f * x);

    float t1a = fmaf(2.0f * lane + 127.0f, L, -s_csum[lane]);
    float t2a = t1a + L - s_lk[lane];
    float t1b = -1e30f, t2b = -1e30f;
    if (lane < 18) {
        int k2 = lane + 32;
        t1b = fmaf(2.0f * k2 + 127.0f, L, -s_csum[k2]);
        t2b = t1b + L - s_lk[k2];
    }
    float m1 = fmaxf(t1a, t1b), m2 = fmaxf(t2a, t2b);
    #pragma unroll
    for (int o = 16; o; o >>= 1) {
        m1 = fmaxf(m1, __shfl_xor_sync(0xffffffffu, m1, o));
        m2 = fmaxf(m2, __shfl_xor_sync(0xffffffffu, m2, o));
    }
    float s1 = __expf(t1a - m1) + (lane < 18 ? __expf(t1b - m1) : 0.0f);
    float s2 = __expf(t2a - m2) + (lane < 18 ? __expf(t2b - m2) : 0.0f);
    #pragma unroll
    for (int o = 16; o; o >>= 1) {
        s1 += __shfl_xor_sync(0xffffffffu, s1, o);
        s2 += __shfl_xor_sync(0xffffffffu, s2, o);
    }
    float lb127 = m1 + logf(s1);
    float lb128 = m2 + logf(s2);
    float diff = fminf(fmaxf(lb128 - lb127, -60.0f), 0.0f);
    float A = fminf(fmaxf(expf(diff), 1e-8f), 1.0f - 1e-6f);

    if (isq) {
        if (lane == 0) {
            g_Aq[j] = A;
            g_Pq[j] = A * x;
            float logC = 127.0f * logf(x) - (128.0f * 1.8378770664093454f) - lb127;
            float ent = -logC - x * A;
            entropy_out[j] = ent;
            s_ent[warp] = ent;
        }
        __syncthreads();
        if (tid < 32) {
            float xe = -2.0f * s_ent[tid];
            float m = xe;
            #pragma unroll
            for (int o = 16; o; o >>= 1) m = fmaxf(m, __shfl_xor_sync(0xffffffffu, m, o));
            float e = expf(xe - m);
            float s = e;
            #pragma unroll
            for (int o = 16; o; o >>= 1) s += __shfl_xor_sync(0xffffffffu, s, o);
            g_tw[(blk - 256) * 32 + tid] = e / s;
        }
    } else if (lane == 0) {
        g_At[j] = A;
        g_Pt[j] = A * x;
    }
}

// ---------------------------------------------------------------------------
// Kernel B: single-product bf16 mma.sync GEMM, BK=64 (4 chunks/tile — HALF
// the barrier/wait convoys of BK=32). 3-stage cp.async ring (stage 32KB:
// A 16K + B 16K), +2 lookahead (<= stages-1), one sync per chunk.
// CTA tile 128x128, 8 warps (2x4), warp tile 64x32, 2 CTA/SM (192KB smem).
// Rows are full 128B lines (64 bf16): standard SW128 swizzle
//   addr(r,c) = r*128 + ((c ^ (r&7)) << 4), c in 0..7.
// ---------------------------------------------------------------------------
#define STG   32768
#define A_HI  0
#define B_HI  16384
#define GEMM_SMEM (3 * STG)

__device__ __forceinline__ uint32_t swz(int r, int c) {
    return (uint32_t)((r * 128) + (((c ^ (r & 7)) << 4)));
}
__device__ __forceinline__ void ldmatrix_x4(uint32_t* r, uint32_t addr) {
    asm volatile("ldmatrix.sync.aligned.m8n8.x4.shared.b16 {%0,%1,%2,%3}, [%4];"
                 : "=r"(r[0]), "=r"(r[1]), "=r"(r[2]), "=r"(r[3]) : "r"(addr));
}
__device__ __forceinline__ void mma_16816(float* d, const uint32_t* a, const uint32_t* b) {
    asm("mma.sync.aligned.m16n8k16.row.col.f32.bf16.bf16.f32 "
        "{%0,%1,%2,%3}, {%4,%5,%6,%7}, {%8,%9}, {%0,%1,%2,%3};"
        : "+f"(d[0]), "+f"(d[1]), "+f"(d[2]), "+f"(d[3])
        : "r"(a[0]), "r"(a[1]), "r"(a[2]), "r"(a[3]), "r"(b[0]), "r"(b[1]));
}
#define CP_ASYNC16(dst, src) \
    asm volatile("cp.async.cg.shared.global [%0], [%1], 16;" :: "r"(dst), "l"(src))
#define CP_COMMIT() asm volatile("cp.async.commit_group;" ::: "memory")
#define CP_WAIT1()  asm volatile("cp.async.wait_group 1;" ::: "memory")
#define CP_WAIT0()  asm volatile("cp.async.wait_group 0;" ::: "memory")

__global__ __launch_bounds__(256, 2)
void score_gemm_mma(const float* __restrict__ Kq, const float* __restrict__ Kt,
                    float* __restrict__ score_global) {
    extern __shared__ char smem[];
    const uint32_t sbase = smem_u32(smem);

    const int tid  = threadIdx.x;
    const int wid  = tid >> 5, lane = tid & 31;
    const int wm   = wid >> 2;          // 0..1 (64 rows)
    const int wn   = wid & 3;           // 0..3 (32 cols)
    const int m0   = blockIdx.y * 128, n0 = blockIdx.x * 128;

    const int lg   = lane >> 3;
    const int lrow = (lane & 7) + (lg & 1) * 8;
    const int lkc  = lg >> 1;

    // per-(fragment, k16-step) smem offsets; chunk index = s*2 + lkc, s in 0..3
    uint32_t aoff[4][4], boff[2][4];
    #pragma unroll
    for (int mf = 0; mf < 4; mf++)
        #pragma unroll
        for (int s = 0; s < 4; s++)
            aoff[mf][s] = swz(wm * 64 + mf * 16 + lrow, s * 2 + lkc);
    #pragma unroll
    for (int pr = 0; pr < 2; pr++)
        #pragma unroll
        for (int s = 0; s < 4; s++)
            boff[pr][s] = swz(wn * 32 + pr * 16 + lrow, s * 2 + lkc);

    float acc[4][4][4];
    #pragma unroll
    for (int i = 0; i < 4; i++)
        #pragma unroll
        for (int j = 0; j < 4; j++)
            #pragma unroll
            for (int r = 0; r < 4; r++) acc[i][j][r] = 0.0f;

    // staging: 128 rows, 2 threads/row, 4 chunks of 16B each
    const int srow = tid >> 1;
    const int ch0  = (tid & 1) * 4;
    uint32_t stoff[4];
    #pragma unroll
    for (int c = 0; c < 4; c++) stoff[c] = swz(srow, ch0 + c);
    const size_t gaRow = (size_t)(m0 + srow) * 256 + ch0 * 8;
    const size_t gbRow = (size_t)(n0 + srow) * 256 + ch0 * 8;

    #define PREFETCH(kc, st) do {                                              \
        const uint32_t sb = sbase + (uint32_t)((st) * STG);                    \
        const size_t gk = (size_t)(kc) * 64;                                   \
        _Pragma("unroll")                                                      \
        for (int c = 0; c < 4; c++) {                                          \
            CP_ASYNC16(sb + A_HI + stoff[c], g_qhi + gaRow + gk + c * 8);      \
            CP_ASYNC16(sb + B_HI + stoff[c], g_thi + gbRow + gk + c * 8);      \
        }                                                                      \
        CP_COMMIT();                                                           \
    } while (0)

    PREFETCH(0, 0);
    PREFETCH(1, 1);

    #pragma unroll
    for (int kc = 0; kc < 4; kc++) {
        const int cur = kc % 3;
        if (kc < 3) CP_WAIT1(); else CP_WAIT0();
        __syncthreads();
        if (kc < 2) PREFETCH(kc + 2, (kc + 2) % 3);

        const uint32_t so = sbase + (uint32_t)(cur * STG);
        #pragma unroll
        for (int s = 0; s < 4; s++) {
            uint32_t ah[4][4];
            #pragma unroll
            for (int mf = 0; mf < 4; mf++)
                ldmatrix_x4(ah[mf], so + A_HI + aoff[mf][s]);
            uint32_t bh01[4], bh23[4];
            ldmatrix_x4(bh01, so + B_HI + boff[0][s]);
            ldmatrix_x4(bh23, so + B_HI + boff[1][s]);
            uint32_t bh[4][2] = {{bh01[0], bh01[2]}, {bh01[1], bh01[3]},
                                 {bh23[0], bh23[2]}, {bh23[1], bh23[3]}};

            #pragma unroll
            for (int mf = 0; mf < 4; mf++)
                #pragma unroll
                for (int nf = 0; nf < 4; nf++)
                    mma_16816(acc[mf][nf], ah[mf], bh[nf]);
        }
    }

    // ---------------- epilogue ----------------
    float at[8], ktv[8], pt[8];
    #pragma unroll
    for (int nf = 0; nf < 4; nf++)
        #pragma unroll
        for (int rb = 0; rb < 2; rb++) {
            int col = n0 + wn * 32 + nf * 8 + (lane & 3) * 2 + rb;
            at[nf * 2 + rb]  = g_At[col];
            ktv[nf * 2 + rb] = fmaxf(Kt[col], 1e-6f);
            pt[nf * 2 + rb]  = g_Pt[col];
        }

    float part[2] = {0.0f, 0.0f};
    #pragma unroll
    for (int mf = 0; mf < 4; mf++) {
        #pragma unroll
        for (int rh = 0; rh < 2; rh++) {
            int row = m0 + wm * 64 + mf * 16 + (lane >> 2) + rh * 8;
            float aq = g_Aq[row];
            float kq = fmaxf(Kq[row], 1e-6f);
            float pq = g_Pq[row];
            float tw = g_tw[row];
            float mx = -1e30f;
            #pragma unroll
            for (int nf = 0; nf < 4; nf++)
                #pragma unroll
                for (int rb = 0; rb < 2; rb++) {
                    int cj = nf * 2 + rb;
                    float beta = 0.5f * (aq * ktv[cj] + at[cj] * kq);
                    float s = fmaf(beta, acc[mf][nf][rh * 2 + rb], -0.5f * (pq + pt[cj]));
                    mx = fmaxf(mx, s);
                }
            mx = fmaxf(mx, __shfl_xor_sync(0xffffffffu, mx, 1));
            mx = fmaxf(mx, __shfl_xor_sync(0xffffffffu, mx, 2));
            part[mf >> 1] += tw * mx;
        }
    }
    #pragma unroll
    for (int g = 0; g < 2; g++) {
        float v = part[g];
        v += __shfl_xor_sync(0xffffffffu, v, 4);
        v += __shfl_xor_sync(0xffffffffu, v, 8);
        v += __shfl_xor_sync(0xffffffffu, v, 16);
        if (lane == 0)
            score_global[(m0 / 32 + wm * 2 + g) * 128 + n0 / 32 + wn] = v;
    }
}

// ---------------------------------------------------------------------------
// Kernel C: logits = score/temp, per-row logsumexp, fused loss (atomicAdd).
// ---------------------------------------------------------------------------
__global__ void softmax_loss_kernel(const float* __restrict__ score,
                                    const float* __restrict__ temp,
                                    float* __restrict__ logits,
                                    float* __restrict__ out_loss) {
    __shared__ float red[4];
    __shared__ float red2[4];
    __shared__ float diag;
    int row = blockIdx.x, t = threadIdx.x;
    float tv = fmaxf(temp[0], 1e-6f);
    float v = score[row * 128 + t] / tv;
    logits[row * 128 + t] = v;
    if (t == row) diag = v;

    float m = v;
    #pragma unroll
    for (int o = 16; o; o >>= 1) m = fmaxf(m, __shfl_xor_sync(0xffffffffu, m, o));
    if ((t & 31) == 0) red[t >> 5] = m;
    __syncthreads();
    m = fmaxf(fmaxf(red[0], red[1]), fmaxf(red[2], red[3]));

    float e = expf(v - m);
    float s = e;
    #pragma unroll
    for (int o = 16; o; o >>= 1) s += __shfl_xor_sync(0xffffffffu, s, o);
    if ((t & 31) == 0) red2[t >> 5] = s;
    __syncthreads();
    if (t == 0) {
        s = red2[0] + red2[1] + red2[2] + red2[3];
        float lse = m + logf(s);
        atomicAdd(out_loss, (lse - diag) * (1.0f / 128.0f));
    }
}

// ---------------------------------------------------------------------------
// Outputs: [0] loss, [1..16385) logits(128x128), then score(128x128), entropy(128x32)
// ---------------------------------------------------------------------------
extern "C" void kernel_launch(void* const* d_in, const int* in_sizes, int n_in,
                              void* d_out, int out_size) {
    const float* q    = (const float*)d_in[0];
    const float* kq   = (const float*)d_in[1];
    const float* t    = (const float*)d_in[2];
    const float* kt   = (const float*)d_in[3];
    const float* temp = (const float*)d_in[4];

    float* out         = (float*)d_out;
    float* out_loss    = out;
    float* out_logits  = out + 1;
    float* out_score   = out + 1 + 128 * 128;
    float* out_entropy = out + 1 + 2 * 128 * 128;

    static int smem_set = 0;
    if (!smem_set) {
        cudaFuncSetAttribute(score_gemm_mma, cudaFuncAttributeMaxDynamicSharedMemorySize, GEMM_SMEM);
        smem_set = 1;
    }

    prep_kernel<<<512, 1024>>>(q, t, kq, kt, out_entropy, out_loss);

    dim3 grid(32, 32);
    score_gemm_mma<<<grid, 256, GEMM_SMEM>>>(kq, kt, out_score);

    softmax_loss_kernel<<<128, 128>>>(out_score, temp, out_logits, out_loss);
}